// round 2
// baseline (speedup 1.0000x reference)
#include <cuda_runtime.h>

#define NH 16
#define DK 64
#define BB 2
#define LL 2048
#define DM 1024

// Scratch for projected Q/K/V in [B, H, L, DK] layout (allowed: __device__ globals)
__device__ float g_q[BB * NH * LL * DK];
__device__ float g_k[BB * NH * LL * DK];
__device__ float g_v[BB * NH * LL * DK];

// ---------------------------------------------------------------------------
// Projection GEMM: out[b,h,l,d] = sum_k X[m,k] * W[n,k] + bias[n]
//   where m = b*LL + l, n = h*64 + d.  M=4096, N=1024, K=1024.
// Tiling: BM=64, BN=64, BK=32; 256 threads, 4x4 micro-tile per thread.
// Column mapping n = n0 + tx + 16*j  (conflict-free smem reads).
// ---------------------------------------------------------------------------
__global__ __launch_bounds__(256)
void proj_kernel(const float* __restrict__ X, const float* __restrict__ W,
                 const float* __restrict__ bias, float* __restrict__ out)
{
    __shared__ float As[32][65];
    __shared__ float Bs[32][65];

    const int tid = threadIdx.x;
    const int m0 = blockIdx.y << 6;
    const int n0 = blockIdx.x << 6;
    const int tx = tid & 15, ty = tid >> 4;
    const int kk = tid & 31, rr = tid >> 5;

    float acc[4][4];
#pragma unroll
    for (int i = 0; i < 4; i++)
#pragma unroll
        for (int j = 0; j < 4; j++) acc[i][j] = 0.f;

    const float* Xp = X + (size_t)m0 * DM + kk;
    const float* Wp = W + (size_t)n0 * DM + kk;

    for (int k0 = 0; k0 < DM; k0 += 32) {
#pragma unroll
        for (int i = 0; i < 8; i++) {
            int mm = rr + (i << 3);
            As[kk][mm] = Xp[(size_t)mm * DM + k0];
            Bs[kk][mm] = Wp[(size_t)mm * DM + k0];
        }
        __syncthreads();
#pragma unroll
        for (int k2 = 0; k2 < 32; k2++) {
            float a[4], b[4];
#pragma unroll
            for (int i = 0; i < 4; i++) a[i] = As[k2][ty * 4 + i];
#pragma unroll
            for (int j = 0; j < 4; j++) b[j] = Bs[k2][tx + (j << 4)];
#pragma unroll
            for (int i = 0; i < 4; i++)
#pragma unroll
                for (int j = 0; j < 4; j++) acc[i][j] += a[i] * b[j];
        }
        __syncthreads();
    }

    const int h = n0 >> 6;  // BN==64 so whole block maps to one head
#pragma unroll
    for (int i = 0; i < 4; i++) {
        int m = m0 + ty * 4 + i;
        int b_ = m >> 11;          // / LL
        int l  = m & (LL - 1);
        float* op = out + (((size_t)(b_ * NH + h) * LL + l) << 6);
#pragma unroll
        for (int j = 0; j < 4; j++) {
            int d = tx + (j << 4);
            op[d] = acc[i][j] + bias[n0 + d];
        }
    }
}

// ---------------------------------------------------------------------------
// Flash-style attention: per (b,h), 64-query tiles stream over 64-key tiles.
// Mask is additive: s + ((hq != hk) ? -1e9 : 0), matching the reference
// (including the degenerate all-masked-row case, where the constant cancels).
// S columns mapped c = tx + 16*j; row stats reduced over 16-lane shfl groups.
// ---------------------------------------------------------------------------
__global__ __launch_bounds__(256)
void attn_kernel(const float* __restrict__ Q, const float* __restrict__ K,
                 const float* __restrict__ V, const int* __restrict__ HQ,
                 const int* __restrict__ HK, float* __restrict__ out)
{
    extern __shared__ float sm[];
    float* Qs = sm;            // 64 x 68
    float* Ks = Qs + 64 * 68;  // 64 x 68
    float* Vs = Ks + 64 * 68;  // 64 x 68
    float* Ps = Vs + 64 * 68;  // 64 x 68
    __shared__ int shk[64];

    const int bh = blockIdx.y;
    const int q0 = blockIdx.x << 6;
    const float* Qb = Q + (size_t)bh * LL * DK;
    const float* Kb = K + (size_t)bh * LL * DK;
    const float* Vb = V + (size_t)bh * LL * DK;
    const int* hqb = HQ + (size_t)bh * LL;
    const int* hkb = HK + (size_t)bh * LL;

    const int tid = threadIdx.x;
    const int tx = tid & 15, ty = tid >> 4;

    // Load Q tile (float4, 68-float pitch keeps 16B alignment: 68*4=272=17*16)
#pragma unroll
    for (int i = 0; i < 4; i++) {
        int idx = (i << 8) + tid;          // float4 index 0..1023
        int row = idx >> 4, c4 = idx & 15;
        float4 v = ((const float4*)(Qb + (size_t)(q0 + row) * DK))[c4];
        *((float4*)(Qs + row * 68) + c4) = v;
    }
    int hqi[4];
#pragma unroll
    for (int i = 0; i < 4; i++) hqi[i] = hqb[q0 + ty * 4 + i];

    float mrow[4], lrow[4], O[4][4];
#pragma unroll
    for (int i = 0; i < 4; i++) {
        mrow[i] = -3.4e38f;
        lrow[i] = 0.f;
#pragma unroll
        for (int j = 0; j < 4; j++) O[i][j] = 0.f;
    }

    for (int k0 = 0; k0 < LL; k0 += 64) {
        // Load K/V tiles + key hashes
#pragma unroll
        for (int i = 0; i < 4; i++) {
            int idx = (i << 8) + tid;
            int row = idx >> 4, c4 = idx & 15;
            *((float4*)(Ks + row * 68) + c4) =
                ((const float4*)(Kb + (size_t)(k0 + row) * DK))[c4];
            *((float4*)(Vs + row * 68) + c4) =
                ((const float4*)(Vb + (size_t)(k0 + row) * DK))[c4];
        }
        if (tid < 64) shk[tid] = hkb[k0 + tid];
        __syncthreads();

        // S = Q @ K^T
        float s[4][4];
#pragma unroll
        for (int i = 0; i < 4; i++)
#pragma unroll
            for (int j = 0; j < 4; j++) s[i][j] = 0.f;
#pragma unroll 8
        for (int kkk = 0; kkk < 64; kkk++) {
            float a[4], b[4];
#pragma unroll
            for (int i = 0; i < 4; i++) a[i] = Qs[(ty * 4 + i) * 68 + kkk];
#pragma unroll
            for (int j = 0; j < 4; j++) b[j] = Ks[(tx + (j << 4)) * 68 + kkk];
#pragma unroll
            for (int i = 0; i < 4; i++)
#pragma unroll
                for (int j = 0; j < 4; j++) s[i][j] += a[i] * b[j];
        }

        // Scale + mask + online softmax
#pragma unroll
        for (int i = 0; i < 4; i++) {
            float tm = -3.4e38f;
#pragma unroll
            for (int j = 0; j < 4; j++) {
                int c = tx + (j << 4);
                float v = s[i][j] * 0.125f + ((hqi[i] != shk[c]) ? -1.0e9f : 0.f);
                s[i][j] = v;
                tm = fmaxf(tm, v);
            }
#pragma unroll
            for (int o = 8; o >= 1; o >>= 1)
                tm = fmaxf(tm, __shfl_xor_sync(0xffffffffu, tm, o));
            float newm = fmaxf(mrow[i], tm);
            float corr = __expf(mrow[i] - newm);
            mrow[i] = newm;
            float ps = 0.f;
#pragma unroll
            for (int j = 0; j < 4; j++) {
                float p = __expf(s[i][j] - newm);
                s[i][j] = p;
                ps += p;
            }
#pragma unroll
            for (int o = 8; o >= 1; o >>= 1)
                ps += __shfl_xor_sync(0xffffffffu, ps, o);
            lrow[i] = lrow[i] * corr + ps;
#pragma unroll
            for (int j = 0; j < 4; j++) O[i][j] *= corr;
        }

        // Write P (the two ty-halves of a warp hit disjoint bank sets)
#pragma unroll
        for (int i = 0; i < 4; i++)
#pragma unroll
            for (int j = 0; j < 4; j++)
                Ps[(ty * 4 + i) * 68 + tx + (j << 4)] = s[i][j];
        __syncthreads();

        // O += P @ V
#pragma unroll 8
        for (int jj = 0; jj < 64; jj++) {
            float p[4], v[4];
#pragma unroll
            for (int i = 0; i < 4; i++) p[i] = Ps[(ty * 4 + i) * 68 + jj];
#pragma unroll
            for (int j = 0; j < 4; j++) v[j] = Vs[jj * 68 + tx + (j << 4)];
#pragma unroll
            for (int i = 0; i < 4; i++)
#pragma unroll
                for (int j = 0; j < 4; j++) O[i][j] += p[i] * v[j];
        }
        __syncthreads();
    }

    // Final normalize + store to [B, L, H*DK]
    const int b_ = bh >> 4, h = bh & 15;
#pragma unroll
    for (int i = 0; i < 4; i++) {
        int l = q0 + ty * 4 + i;
        float inv = 1.f / lrow[i];
        float* op = out + (size_t)(b_ * LL + l) * DM + (h << 6);
#pragma unroll
        for (int j = 0; j < 4; j++) op[tx + (j << 4)] = O[i][j] * inv;
    }
}

// ---------------------------------------------------------------------------
// Launch
// ---------------------------------------------------------------------------
extern "C" void kernel_launch(void* const* d_in, const int* in_sizes, int n_in,
                              void* d_out, int out_size)
{
    const float* query = (const float*)d_in[0];
    const float* key_  = (const float*)d_in[1];
    const float* value = (const float*)d_in[2];
    const int*   hq    = (const int*)d_in[3];
    const int*   hk    = (const int*)d_in[4];
    const float* Wq    = (const float*)d_in[5];
    const float* bq    = (const float*)d_in[6];
    const float* Wk    = (const float*)d_in[7];
    const float* bk    = (const float*)d_in[8];
    const float* Wv    = (const float*)d_in[9];
    const float* bv    = (const float*)d_in[10];

    float *qp, *kp, *vp;
    cudaGetSymbolAddress((void**)&qp, g_q);
    cudaGetSymbolAddress((void**)&kp, g_k);
    cudaGetSymbolAddress((void**)&vp, g_v);

    dim3 pg(DM / 64, (BB * LL) / 64);
    proj_kernel<<<pg, 256>>>(query, Wq, bq, qp);
    proj_kernel<<<pg, 256>>>(key_,  Wk, bk, kp);
    proj_kernel<<<pg, 256>>>(value, Wv, bv, vp);

    int smem = 4 * 64 * 68 * (int)sizeof(float);  // 69632 B
    cudaFuncSetAttribute(attn_kernel, cudaFuncAttributeMaxDynamicSharedMemorySize, smem);
    dim3 ag(LL / 64, BB * NH);
    attn_kernel<<<ag, 256, smem>>>(qp, kp, vp, hq, hk, (float*)d_out);
}

// round 3
// speedup vs baseline: 1.0003x; 1.0003x over previous
#include <cuda_runtime.h>

#define NH 16
#define DK 64
#define BB 2
#define LL 2048
#define DM 1024

// Scratch for projected Q/K/V in [B, H, L, DK] layout (allowed: __device__ globals)
__device__ float g_q[BB * NH * LL * DK];
__device__ float g_k[BB * NH * LL * DK];
__device__ float g_v[BB * NH * LL * DK];

// ---------------------------------------------------------------------------
// Projection GEMM: out[b,h,l,d] = sum_k X[m,k] * W[n,k] + bias[n]
//   where m = b*LL + l, n = h*64 + d.  M=4096, N=1024, K=1024.
// Tiling: BM=64, BN=64, BK=32; 256 threads, 4x4 micro-tile per thread.
// Column mapping n = n0 + tx + 16*j  (conflict-free smem reads).
// ---------------------------------------------------------------------------
__global__ __launch_bounds__(256)
void proj_kernel(const float* __restrict__ X, const float* __restrict__ W,
                 const float* __restrict__ bias, float* __restrict__ out)
{
    __shared__ float As[32][65];
    __shared__ float Bs[32][65];

    const int tid = threadIdx.x;
    const int m0 = blockIdx.y << 6;
    const int n0 = blockIdx.x << 6;
    const int tx = tid & 15, ty = tid >> 4;
    const int kk = tid & 31, rr = tid >> 5;

    float acc[4][4];
#pragma unroll
    for (int i = 0; i < 4; i++)
#pragma unroll
        for (int j = 0; j < 4; j++) acc[i][j] = 0.f;

    const float* Xp = X + (size_t)m0 * DM + kk;
    const float* Wp = W + (size_t)n0 * DM + kk;

    for (int k0 = 0; k0 < DM; k0 += 32) {
#pragma unroll
        for (int i = 0; i < 8; i++) {
            int mm = rr + (i << 3);
            As[kk][mm] = Xp[(size_t)mm * DM + k0];
            Bs[kk][mm] = Wp[(size_t)mm * DM + k0];
        }
        __syncthreads();
#pragma unroll
        for (int k2 = 0; k2 < 32; k2++) {
            float a[4], b[4];
#pragma unroll
            for (int i = 0; i < 4; i++) a[i] = As[k2][ty * 4 + i];
#pragma unroll
            for (int j = 0; j < 4; j++) b[j] = Bs[k2][tx + (j << 4)];
#pragma unroll
            for (int i = 0; i < 4; i++)
#pragma unroll
                for (int j = 0; j < 4; j++) acc[i][j] += a[i] * b[j];
        }
        __syncthreads();
    }

    const int h = n0 >> 6;  // BN==64 so whole block maps to one head
#pragma unroll
    for (int i = 0; i < 4; i++) {
        int m = m0 + ty * 4 + i;
        int b_ = m >> 11;          // / LL
        int l  = m & (LL - 1);
        float* op = out + (((size_t)(b_ * NH + h) * LL + l) << 6);
#pragma unroll
        for (int j = 0; j < 4; j++) {
            int d = tx + (j << 4);
            op[d] = acc[i][j] + bias[n0 + d];
        }
    }
}

// ---------------------------------------------------------------------------
// Flash-style attention: per (b,h), 64-query tiles stream over 64-key tiles.
// Mask is additive: s + ((hq != hk) ? -1e9 : 0), matching the reference
// (including the degenerate all-masked-row case, where the constant cancels).
// S columns mapped c = tx + 16*j; row stats reduced over 16-lane shfl groups.
// ---------------------------------------------------------------------------
__global__ __launch_bounds__(256)
void attn_kernel(const float* __restrict__ Q, const float* __restrict__ K,
                 const float* __restrict__ V, const int* __restrict__ HQ,
                 const int* __restrict__ HK, float* __restrict__ out)
{
    extern __shared__ float sm[];
    float* Qs = sm;            // 64 x 68
    float* Ks = Qs + 64 * 68;  // 64 x 68
    float* Vs = Ks + 64 * 68;  // 64 x 68
    float* Ps = Vs + 64 * 68;  // 64 x 68
    __shared__ int shk[64];

    const int bh = blockIdx.y;
    const int q0 = blockIdx.x << 6;
    const float* Qb = Q + (size_t)bh * LL * DK;
    const float* Kb = K + (size_t)bh * LL * DK;
    const float* Vb = V + (size_t)bh * LL * DK;
    const int* hqb = HQ + (size_t)bh * LL;
    const int* hkb = HK + (size_t)bh * LL;

    const int tid = threadIdx.x;
    const int tx = tid & 15, ty = tid >> 4;

    // Load Q tile (float4, 68-float pitch keeps 16B alignment: 68*4=272=17*16)
#pragma unroll
    for (int i = 0; i < 4; i++) {
        int idx = (i << 8) + tid;          // float4 index 0..1023
        int row = idx >> 4, c4 = idx & 15;
        float4 v = ((const float4*)(Qb + (size_t)(q0 + row) * DK))[c4];
        *((float4*)(Qs + row * 68) + c4) = v;
    }
    int hqi[4];
#pragma unroll
    for (int i = 0; i < 4; i++) hqi[i] = hqb[q0 + ty * 4 + i];

    float mrow[4], lrow[4], O[4][4];
#pragma unroll
    for (int i = 0; i < 4; i++) {
        mrow[i] = -3.4e38f;
        lrow[i] = 0.f;
#pragma unroll
        for (int j = 0; j < 4; j++) O[i][j] = 0.f;
    }

    for (int k0 = 0; k0 < LL; k0 += 64) {
        // Load K/V tiles + key hashes
#pragma unroll
        for (int i = 0; i < 4; i++) {
            int idx = (i << 8) + tid;
            int row = idx >> 4, c4 = idx & 15;
            *((float4*)(Ks + row * 68) + c4) =
                ((const float4*)(Kb + (size_t)(k0 + row) * DK))[c4];
            *((float4*)(Vs + row * 68) + c4) =
                ((const float4*)(Vb + (size_t)(k0 + row) * DK))[c4];
        }
        if (tid < 64) shk[tid] = hkb[k0 + tid];
        __syncthreads();

        // S = Q @ K^T
        float s[4][4];
#pragma unroll
        for (int i = 0; i < 4; i++)
#pragma unroll
            for (int j = 0; j < 4; j++) s[i][j] = 0.f;
#pragma unroll 8
        for (int kkk = 0; kkk < 64; kkk++) {
            float a[4], b[4];
#pragma unroll
            for (int i = 0; i < 4; i++) a[i] = Qs[(ty * 4 + i) * 68 + kkk];
#pragma unroll
            for (int j = 0; j < 4; j++) b[j] = Ks[(tx + (j << 4)) * 68 + kkk];
#pragma unroll
            for (int i = 0; i < 4; i++)
#pragma unroll
                for (int j = 0; j < 4; j++) s[i][j] += a[i] * b[j];
        }

        // Scale + mask + online softmax
#pragma unroll
        for (int i = 0; i < 4; i++) {
            float tm = -3.4e38f;
#pragma unroll
            for (int j = 0; j < 4; j++) {
                int c = tx + (j << 4);
                float v = s[i][j] * 0.125f + ((hqi[i] != shk[c]) ? -1.0e9f : 0.f);
                s[i][j] = v;
                tm = fmaxf(tm, v);
            }
#pragma unroll
            for (int o = 8; o >= 1; o >>= 1)
                tm = fmaxf(tm, __shfl_xor_sync(0xffffffffu, tm, o));
            float newm = fmaxf(mrow[i], tm);
            float corr = __expf(mrow[i] - newm);
            mrow[i] = newm;
            float ps = 0.f;
#pragma unroll
            for (int j = 0; j < 4; j++) {
                float p = __expf(s[i][j] - newm);
                s[i][j] = p;
                ps += p;
            }
#pragma unroll
            for (int o = 8; o >= 1; o >>= 1)
                ps += __shfl_xor_sync(0xffffffffu, ps, o);
            lrow[i] = lrow[i] * corr + ps;
#pragma unroll
            for (int j = 0; j < 4; j++) O[i][j] *= corr;
        }

        // Write P (the two ty-halves of a warp hit disjoint bank sets)
#pragma unroll
        for (int i = 0; i < 4; i++)
#pragma unroll
            for (int j = 0; j < 4; j++)
                Ps[(ty * 4 + i) * 68 + tx + (j << 4)] = s[i][j];
        __syncthreads();

        // O += P @ V
#pragma unroll 8
        for (int jj = 0; jj < 64; jj++) {
            float p[4], v[4];
#pragma unroll
            for (int i = 0; i < 4; i++) p[i] = Ps[(ty * 4 + i) * 68 + jj];
#pragma unroll
            for (int j = 0; j < 4; j++) v[j] = Vs[jj * 68 + tx + (j << 4)];
#pragma unroll
            for (int i = 0; i < 4; i++)
#pragma unroll
                for (int j = 0; j < 4; j++) O[i][j] += p[i] * v[j];
        }
        __syncthreads();
    }

    // Final normalize + store to [B, L, H*DK]
    const int b_ = bh >> 4, h = bh & 15;
#pragma unroll
    for (int i = 0; i < 4; i++) {
        int l = q0 + ty * 4 + i;
        float inv = 1.f / lrow[i];
        float* op = out + (size_t)(b_ * LL + l) * DM + (h << 6);
#pragma unroll
        for (int j = 0; j < 4; j++) op[tx + (j << 4)] = O[i][j] * inv;
    }
}

// ---------------------------------------------------------------------------
// Launch
// ---------------------------------------------------------------------------
extern "C" void kernel_launch(void* const* d_in, const int* in_sizes, int n_in,
                              void* d_out, int out_size)
{
    const float* query = (const float*)d_in[0];
    const float* key_  = (const float*)d_in[1];
    const float* value = (const float*)d_in[2];
    const int*   hq    = (const int*)d_in[3];
    const int*   hk    = (const int*)d_in[4];
    const float* Wq    = (const float*)d_in[5];
    const float* bq    = (const float*)d_in[6];
    const float* Wk    = (const float*)d_in[7];
    const float* bk    = (const float*)d_in[8];
    const float* Wv    = (const float*)d_in[9];
    const float* bv    = (const float*)d_in[10];

    float *qp, *kp, *vp;
    cudaGetSymbolAddress((void**)&qp, g_q);
    cudaGetSymbolAddress((void**)&kp, g_k);
    cudaGetSymbolAddress((void**)&vp, g_v);

    dim3 pg(DM / 64, (BB * LL) / 64);
    proj_kernel<<<pg, 256>>>(query, Wq, bq, qp);
    proj_kernel<<<pg, 256>>>(key_,  Wk, bk, kp);
    proj_kernel<<<pg, 256>>>(value, Wv, bv, vp);

    int smem = 4 * 64 * 68 * (int)sizeof(float);  // 69632 B
    cudaFuncSetAttribute(attn_kernel, cudaFuncAttributeMaxDynamicSharedMemorySize, smem);
    dim3 ag(LL / 64, BB * NH);
    attn_kernel<<<ag, 256, smem>>>(qp, kp, vp, hq, hk, (float*)d_out);
}

// round 6
// speedup vs baseline: 2.2801x; 2.2793x over previous
#include <cuda_runtime.h>
#include <cuda_bf16.h>
#include <stdint.h>

#define NH 16
#define DK 64
#define BB 2
#define LL 2048
#define DM 1024
#define NEG -1.0e9f
#define NX (BB*LL*DM)
#define NW (DM*DM)
#define NE (BB*NH*LL*DK)

__device__ uint16_t s_xh[3*NX], s_xl[3*NX];
__device__ uint16_t s_wh[3*NW], s_wl[3*NW];
__device__ uint16_t g_qh[NE], g_ql[NE], g_kh[NE], g_kl[NE];
__device__ uint16_t g_vh[NE], g_vl[NE];   // transposed [b,h,d,l]

__device__ __forceinline__ uint16_t bfh(float x) {
    __nv_bfloat16 b = __float2bfloat16_rn(x);
    return __bfloat16_as_ushort(b);
}
__device__ __forceinline__ float bf2f(uint16_t u) {
    return __bfloat162float(__ushort_as_bfloat16(u));
}
__device__ __forceinline__ void mma16816(float* c, const uint32_t* a,
                                         uint32_t b0, uint32_t b1) {
    asm volatile(
        "mma.sync.aligned.m16n8k16.row.col.f32.bf16.bf16.f32 "
        "{%0,%1,%2,%3},{%4,%5,%6,%7},{%8,%9},{%0,%1,%2,%3};\n"
        : "+f"(c[0]), "+f"(c[1]), "+f"(c[2]), "+f"(c[3])
        : "r"(a[0]), "r"(a[1]), "r"(a[2]), "r"(a[3]), "r"(b0), "r"(b1));
}

// ---------------- split fp32 -> bf16 hi/lo ----------------
__global__ void split_k(const float* __restrict__ in, uint16_t* __restrict__ hi,
                        uint16_t* __restrict__ lo, int n) {
    int i = blockIdx.x * blockDim.x + threadIdx.x;
    if (i < n) {
        float x = in[i];
        uint16_t h = bfh(x);
        hi[i] = h;
        lo[i] = bfh(x - bf2f(h));
    }
}

// ---------------- projection GEMM (bf16x3 mma) ----------------
// out = X[m,k] @ W[n,k]^T + bias. M=4096,N=1024,K=1024. BM=128,BN=64,BK=64.
template<bool TRANSV>
__global__ __launch_bounds__(256)
void proj_mma(const uint16_t* __restrict__ Xh, const uint16_t* __restrict__ Xl,
              const uint16_t* __restrict__ Wh, const uint16_t* __restrict__ Wl,
              const float* __restrict__ bias,
              uint16_t* __restrict__ Oh, uint16_t* __restrict__ Ol)
{
    __shared__ uint32_t sm_[12288];             // 48KB
    uint32_t* Ah = sm_;                         // [128][32] pairs
    uint32_t* Al = sm_ + 4096;
    uint32_t* Bh = sm_ + 8192;                  // [64][32]
    uint32_t* Bl = sm_ + 10240;

    const int tid = threadIdx.x, warp = tid >> 5, lane = tid & 31;
    const int gr = lane >> 2, tg = lane & 3;
    const int m0 = blockIdx.y << 7, n0 = blockIdx.x << 6;
    const int wm = (warp >> 1) << 5, wn = (warp & 1) << 5;
    const int u = tid & 7, r = tid >> 3;        // uint4 loads

    float C[2][4][4];
#pragma unroll
    for (int i = 0; i < 2; i++)
#pragma unroll
        for (int j = 0; j < 4; j++)
#pragma unroll
            for (int e = 0; e < 4; e++) C[i][j][e] = 0.f;

    for (int k0 = 0; k0 < DM; k0 += 64) {
        __syncthreads();
#pragma unroll
        for (int p = 0; p < 4; p++) {
            int rr = r + (p << 5);
            int idx = rr * 32 + ((u * 4) ^ ((rr & 7) << 2));
            *(uint4*)(Ah + idx) = *((const uint4*)(Xh + (size_t)(m0 + rr) * DM + k0) + u);
            *(uint4*)(Al + idx) = *((const uint4*)(Xl + (size_t)(m0 + rr) * DM + k0) + u);
        }
#pragma unroll
        for (int p = 0; p < 2; p++) {
            int rr = r + (p << 5);
            int idx = rr * 32 + ((u * 4) ^ ((rr & 7) << 2));
            *(uint4*)(Bh + idx) = *((const uint4*)(Wh + (size_t)(n0 + rr) * DM + k0) + u);
            *(uint4*)(Bl + idx) = *((const uint4*)(Wl + (size_t)(n0 + rr) * DM + k0) + u);
        }
        __syncthreads();
#pragma unroll
        for (int kk = 0; kk < 4; kk++) {
            const int i0 = (kk * 8 + tg) ^ (gr << 2);
            const int i1 = (kk * 8 + 4 + tg) ^ (gr << 2);
            uint32_t ah[2][4], al[2][4];
#pragma unroll
            for (int mi = 0; mi < 2; mi++) {
                int rb = (wm + (mi << 4) + gr) * 32;
                ah[mi][0] = Ah[rb + i0]; ah[mi][1] = Ah[rb + 256 + i0];
                ah[mi][2] = Ah[rb + i1]; ah[mi][3] = Ah[rb + 256 + i1];
                al[mi][0] = Al[rb + i0]; al[mi][1] = Al[rb + 256 + i0];
                al[mi][2] = Al[rb + i1]; al[mi][3] = Al[rb + 256 + i1];
            }
#pragma unroll
            for (int nj = 0; nj < 4; nj++) {
                int rb = (wn + (nj << 3) + gr) * 32;
                uint32_t b0h = Bh[rb + i0], b1h = Bh[rb + i1];
                uint32_t b0l = Bl[rb + i0], b1l = Bl[rb + i1];
#pragma unroll
                for (int mi = 0; mi < 2; mi++) {
                    mma16816(C[mi][nj], ah[mi], b0h, b1h);
                    mma16816(C[mi][nj], ah[mi], b0l, b1l);
                    mma16816(C[mi][nj], al[mi], b0h, b1h);
                }
            }
        }
    }

    const int h = n0 >> 6;
#pragma unroll
    for (int mi = 0; mi < 2; mi++)
#pragma unroll
        for (int nj = 0; nj < 4; nj++) {
            int n = n0 + wn + (nj << 3) + 2 * tg;
            float b0 = bias[n], b1 = bias[n + 1];
            int d = n & 63;
#pragma unroll
            for (int e = 0; e < 2; e++) {
                int m = m0 + wm + (mi << 4) + gr + e * 8;
                int b_ = m >> 11, l = m & (LL - 1);
                float x0 = C[mi][nj][e * 2] + b0;
                float x1 = C[mi][nj][e * 2 + 1] + b1;
                uint16_t h0 = bfh(x0), h1 = bfh(x1);
                uint16_t l0 = bfh(x0 - bf2f(h0)), l1 = bfh(x1 - bf2f(h1));
                if (TRANSV) {
                    size_t t = ((size_t)(b_ * NH + h) * DK + d) * LL + l;
                    Oh[t] = h0; Ol[t] = l0;
                    Oh[t + LL] = h1; Ol[t + LL] = l1;
                } else {
                    size_t t = ((size_t)(b_ * NH + h) * LL + l) * DK + d;
                    *(uint32_t*)(Oh + t) = (uint32_t)h0 | ((uint32_t)h1 << 16);
                    *(uint32_t*)(Ol + t) = (uint32_t)l0 | ((uint32_t)l1 << 16);
                }
            }
        }
}

// ---------------- attention (bf16x3 mma, flash-style) ----------------
__global__ __launch_bounds__(256)
void attn(const uint16_t* __restrict__ Qh, const uint16_t* __restrict__ Ql,
          const uint16_t* __restrict__ Kh_, const uint16_t* __restrict__ Kl_,
          const uint16_t* __restrict__ Vh_, const uint16_t* __restrict__ Vl_,
          const int* __restrict__ HQ, const int* __restrict__ HK,
          float* __restrict__ out)
{
    __shared__ uint32_t pool[8192];             // 32KB
    __shared__ float stats[4][16][2][2];        // [wm][row][wn][max/sum]
    __shared__ int shk[64];
    uint32_t* Kh = pool;
    uint32_t* Kl = pool + 2048;
    uint32_t* Vh = pool + 4096;
    uint32_t* Vl = pool + 6144;

    const int tid = threadIdx.x, warp = tid >> 5, lane = tid & 31;
    const int gr = lane >> 2, tg = lane & 3;
    const int wm = warp >> 1, wn = warp & 1;
    const int bh = blockIdx.y, q0 = blockIdx.x << 6;
    const size_t qkb = (size_t)bh * LL * DK;
    const size_t vb = (size_t)bh * DK * LL;
    const int u = tid & 7, r = tid >> 3;

    // Q tile -> pool (temp), then extract fragments to registers
#pragma unroll
    for (int p = 0; p < 2; p++) {
        int rr = r + (p << 5);
        int idx = rr * 32 + ((u * 4) ^ ((rr & 7) << 2));
        *(uint4*)(Kh + idx) = *((const uint4*)(Qh + qkb + (size_t)(q0 + rr) * DK) + u);
        *(uint4*)(Kl + idx) = *((const uint4*)(Ql + qkb + (size_t)(q0 + rr) * DK) + u);
    }
    __syncthreads();
    uint32_t qh[4][4], ql[4][4];
    {
        int rb = (wm * 16 + gr) * 32, s = gr << 2;
#pragma unroll
        for (int kt = 0; kt < 4; kt++) {
            int i0 = (kt * 8 + tg) ^ s, i1 = (kt * 8 + 4 + tg) ^ s;
            qh[kt][0] = Kh[rb + i0]; qh[kt][1] = Kh[rb + 256 + i0];
            qh[kt][2] = Kh[rb + i1]; qh[kt][3] = Kh[rb + 256 + i1];
            ql[kt][0] = Kl[rb + i0]; ql[kt][1] = Kl[rb + 256 + i0];
            ql[kt][2] = Kl[rb + i1]; ql[kt][3] = Kl[rb + 256 + i1];
        }
    }
    const int hq0 = HQ[bh * LL + q0 + wm * 16 + gr];
    const int hq1 = HQ[bh * LL + q0 + wm * 16 + gr + 8];

    float O[8][4];
#pragma unroll
    for (int j = 0; j < 8; j++)
#pragma unroll
        for (int e = 0; e < 4; e++) O[j][e] = 0.f;
    float mr0 = -3.4e38f, mr1 = -3.4e38f, lr0 = 0.f, lr1 = 0.f;

    for (int k0 = 0; k0 < LL; k0 += 64) {
        __syncthreads();   // (a) prior smem reads done
#pragma unroll
        for (int p = 0; p < 2; p++) {
            int rr = r + (p << 5);
            int idx = rr * 32 + ((u * 4) ^ ((rr & 7) << 2));
            *(uint4*)(Kh + idx) = *((const uint4*)(Kh_ + qkb + (size_t)(k0 + rr) * DK) + u);
            *(uint4*)(Kl + idx) = *((const uint4*)(Kl_ + qkb + (size_t)(k0 + rr) * DK) + u);
            *(uint4*)(Vh + idx) = *((const uint4*)(Vh_ + vb + (size_t)rr * LL + k0) + u);
            *(uint4*)(Vl + idx) = *((const uint4*)(Vl_ + vb + (size_t)rr * LL + k0) + u);
        }
        if (tid < 64) shk[tid] = HK[bh * LL + k0 + tid];
        __syncthreads();   // (b) tiles ready

        // S = Q K^T  (warp: 16q x 32keys as 4 n-tiles)
        float S[4][4];
#pragma unroll
        for (int j = 0; j < 4; j++)
#pragma unroll
            for (int e = 0; e < 4; e++) S[j][e] = 0.f;
#pragma unroll
        for (int nj = 0; nj < 4; nj++) {
            int rb = (wn * 32 + nj * 8 + gr) * 32, s = gr << 2;
#pragma unroll
            for (int kt = 0; kt < 4; kt++) {
                int i0 = (kt * 8 + tg) ^ s, i1 = (kt * 8 + 4 + tg) ^ s;
                uint32_t b0h = Kh[rb + i0], b1h = Kh[rb + i1];
                uint32_t b0l = Kl[rb + i0], b1l = Kl[rb + i1];
                mma16816(S[nj], qh[kt], b0h, b1h);
                mma16816(S[nj], qh[kt], b0l, b1l);
                mma16816(S[nj], ql[kt], b0h, b1h);
            }
        }
        // scale + mask + row max (rows gr and gr+8)
        float m0 = -3.4e38f, m1 = -3.4e38f;
#pragma unroll
        for (int nj = 0; nj < 4; nj++) {
            int c = wn * 32 + nj * 8 + 2 * tg;
            int k0h = shk[c], k1h = shk[c + 1];
            S[nj][0] = S[nj][0] * 0.125f + ((hq0 != k0h) ? NEG : 0.f);
            S[nj][1] = S[nj][1] * 0.125f + ((hq0 != k1h) ? NEG : 0.f);
            S[nj][2] = S[nj][2] * 0.125f + ((hq1 != k0h) ? NEG : 0.f);
            S[nj][3] = S[nj][3] * 0.125f + ((hq1 != k1h) ? NEG : 0.f);
            m0 = fmaxf(m0, fmaxf(S[nj][0], S[nj][1]));
            m1 = fmaxf(m1, fmaxf(S[nj][2], S[nj][3]));
        }
        m0 = fmaxf(m0, __shfl_xor_sync(0xffffffffu, m0, 1));
        m0 = fmaxf(m0, __shfl_xor_sync(0xffffffffu, m0, 2));
        m1 = fmaxf(m1, __shfl_xor_sync(0xffffffffu, m1, 1));
        m1 = fmaxf(m1, __shfl_xor_sync(0xffffffffu, m1, 2));
        if (tg == 0) {
            stats[wm][gr][wn][0] = m0;
            stats[wm][gr + 8][wn][0] = m1;
        }
        __syncthreads();   // (c)
        float nm0 = fmaxf(mr0, fmaxf(stats[wm][gr][0][0], stats[wm][gr][1][0]));
        float nm1 = fmaxf(mr1, fmaxf(stats[wm][gr + 8][0][0], stats[wm][gr + 8][1][0]));
        float cr0 = __expf(mr0 - nm0), cr1 = __expf(mr1 - nm1);
        mr0 = nm0; mr1 = nm1;
        float ps0 = 0.f, ps1 = 0.f;
#pragma unroll
        for (int nj = 0; nj < 4; nj++) {
            S[nj][0] = __expf(S[nj][0] - nm0);
            S[nj][1] = __expf(S[nj][1] - nm0);
            S[nj][2] = __expf(S[nj][2] - nm1);
            S[nj][3] = __expf(S[nj][3] - nm1);
            ps0 += S[nj][0] + S[nj][1];
            ps1 += S[nj][2] + S[nj][3];
        }
        ps0 += __shfl_xor_sync(0xffffffffu, ps0, 1);
        ps0 += __shfl_xor_sync(0xffffffffu, ps0, 2);
        ps1 += __shfl_xor_sync(0xffffffffu, ps1, 1);
        ps1 += __shfl_xor_sync(0xffffffffu, ps1, 2);
        if (tg == 0) {
            stats[wm][gr][wn][1] = ps0;
            stats[wm][gr + 8][wn][1] = ps1;
        }
        __syncthreads();   // (d)
        lr0 = lr0 * cr0 + stats[wm][gr][0][1] + stats[wm][gr][1][1];
        lr1 = lr1 * cr1 + stats[wm][gr + 8][0][1] + stats[wm][gr + 8][1][1];
#pragma unroll
        for (int j = 0; j < 8; j++) {
            O[j][0] *= cr0; O[j][1] *= cr0;
            O[j][2] *= cr1; O[j][3] *= cr1;
        }
        // O += P V  (P reused from S registers; split hi/lo on the fly)
        // A-fragment order (PTX): a0=P[gr][lo], a1=P[gr+8][lo], a2=P[gr][hi], a3=P[gr+8][hi]
        // which is exactly q=0..3 below — no reordering needed.
#pragma unroll
        for (int kt2 = 0; kt2 < 2; kt2++) {
            uint32_t ah[4], al[4];
#pragma unroll
            for (int q = 0; q < 4; q++) {
                const float* ps = S[2 * kt2 + (q >> 1)];
                float p0 = ps[(q & 1) * 2], p1 = ps[(q & 1) * 2 + 1];
                uint16_t h0 = bfh(p0), h1 = bfh(p1);
                ah[q] = (uint32_t)h0 | ((uint32_t)h1 << 16);
                uint16_t e0 = bfh(p0 - bf2f(h0)), e1 = bfh(p1 - bf2f(h1));
                al[q] = (uint32_t)e0 | ((uint32_t)e1 << 16);
            }
            int s = gr << 2;
            int i0 = (wn * 16 + kt2 * 8 + tg) ^ s;
            int i1 = (wn * 16 + kt2 * 8 + 4 + tg) ^ s;
#pragma unroll
            for (int nd = 0; nd < 8; nd++) {
                int rb = (nd * 8 + gr) * 32;
                uint32_t b0h = Vh[rb + i0], b1h = Vh[rb + i1];
                uint32_t b0l = Vl[rb + i0], b1l = Vl[rb + i1];
                mma16816(O[nd], ah, b0h, b1h);
                mma16816(O[nd], ah, b0l, b1l);
                mma16816(O[nd], al, b0h, b1h);
            }
        }
    }

    // combine wn partials via smem, scale by 1/l, store
    __syncthreads();
    float* osum = (float*)pool;   // [wm][16][66]
    if (wn == 1) {
#pragma unroll
        for (int nd = 0; nd < 8; nd++) {
            int d = nd * 8 + 2 * tg;
            int b0 = wm * 1056 + gr * 66 + d;
            osum[b0] = O[nd][0]; osum[b0 + 1] = O[nd][1];
            int b1 = wm * 1056 + (gr + 8) * 66 + d;
            osum[b1] = O[nd][2]; osum[b1 + 1] = O[nd][3];
        }
    }
    __syncthreads();
    if (wn == 0) {
        float i0 = 1.f / lr0, i1 = 1.f / lr1;
        int b_ = bh >> 4, hh = bh & 15;
        size_t rowa = ((size_t)b_ * LL + q0 + wm * 16 + gr) * DM + hh * 64;
        size_t rowb = rowa + 8 * DM;
#pragma unroll
        for (int nd = 0; nd < 8; nd++) {
            int d = nd * 8 + 2 * tg;
            int ba = wm * 1056 + gr * 66 + d;
            int bb = wm * 1056 + (gr + 8) * 66 + d;
            float2 v0 = make_float2((O[nd][0] + osum[ba]) * i0,
                                    (O[nd][1] + osum[ba + 1]) * i0);
            float2 v1 = make_float2((O[nd][2] + osum[bb]) * i1,
                                    (O[nd][3] + osum[bb + 1]) * i1);
            *(float2*)(out + rowa + d) = v0;
            *(float2*)(out + rowb + d) = v1;
        }
    }
}

// ---------------- launch ----------------
extern "C" void kernel_launch(void* const* d_in, const int* in_sizes, int n_in,
                              void* d_out, int out_size)
{
    const float* X[3] = {(const float*)d_in[0], (const float*)d_in[1], (const float*)d_in[2]};
    const int* hq = (const int*)d_in[3];
    const int* hk = (const int*)d_in[4];
    const float* W[3] = {(const float*)d_in[5], (const float*)d_in[7], (const float*)d_in[9]};
    const float* Bv[3] = {(const float*)d_in[6], (const float*)d_in[8], (const float*)d_in[10]};

    uint16_t *xh, *xl, *wh, *wl, *qh, *ql, *kh, *kl, *vh, *vl;
    cudaGetSymbolAddress((void**)&xh, s_xh);
    cudaGetSymbolAddress((void**)&xl, s_xl);
    cudaGetSymbolAddress((void**)&wh, s_wh);
    cudaGetSymbolAddress((void**)&wl, s_wl);
    cudaGetSymbolAddress((void**)&qh, g_qh);
    cudaGetSymbolAddress((void**)&ql, g_ql);
    cudaGetSymbolAddress((void**)&kh, g_kh);
    cudaGetSymbolAddress((void**)&kl, g_kl);
    cudaGetSymbolAddress((void**)&vh, g_vh);
    cudaGetSymbolAddress((void**)&vl, g_vl);

    for (int i = 0; i < 3; i++) {
        split_k<<<NX / 256, 256>>>(X[i], xh + (size_t)i * NX, xl + (size_t)i * NX, NX);
        split_k<<<NW / 256, 256>>>(W[i], wh + (size_t)i * NW, wl + (size_t)i * NW, NW);
    }
    dim3 pg(DM / 64, (BB * LL) / 128);
    proj_mma<false><<<pg, 256>>>(xh, xl, wh, wl, Bv[0], qh, ql);
    proj_mma<false><<<pg, 256>>>(xh + (size_t)NX, xl + (size_t)NX,
                                 wh + (size_t)NW, wl + (size_t)NW, Bv[1], kh, kl);
    proj_mma<true><<<pg, 256>>>(xh + (size_t)2 * NX, xl + (size_t)2 * NX,
                                wh + (size_t)2 * NW, wl + (size_t)2 * NW, Bv[2], vh, vl);
    dim3 ag(LL / 64, BB * NH);
    attn<<<ag, 256>>>(qh, ql, kh, kl, vh, vl, hq, hk, (float*)d_out);
}